// round 2
// baseline (speedup 1.0000x reference)
#include <cuda_runtime.h>
#include <cuda_bf16.h>

// Problem constants
#define BATCH 64
#define SEQ   197
#define EDIM  768
#define NH    12
#define HD    64
#define MROWS (BATCH * SEQ)          // 12608
#define PERB  (SEQ * EDIM)           // 151296 floats per batch
#define PERH  (SEQ * HD)             // 12608 floats per head-chunk

// Intermediate buffers (static device globals: no runtime allocation)
__device__ float g_Q[MROWS * EDIM];
__device__ float g_K[MROWS * EDIM];
__device__ float g_V[MROWS * EDIM];
__device__ float g_AO[MROWS * EDIM];

// ---------------------------------------------------------------------------
// NT GEMM body: C[M,N] = A[M,K] @ B[N,K]^T + bias[N]
// M = 12608, N = 768, K = 768. BM=BN=128, BK=8, 256 threads, 8x8 per thread.
// Both A and B are K-contiguous (row-major), so both tiles are stored
// transposed in smem: As[k][m], Bs[k][n].
// ---------------------------------------------------------------------------
__device__ __forceinline__ void gemm_nt_body(
    const float* __restrict__ A,
    const float* __restrict__ B,
    const float* __restrict__ bias,
    float* __restrict__ C)
{
    __shared__ float As[8][128];
    __shared__ float Bs[8][128];

    const int tid = threadIdx.x;
    const int bm = blockIdx.y * 128;
    const int bn = blockIdx.x * 128;

    // Global->smem loading assignment: 128 rows x 8 k -> 1024 floats,
    // 256 threads x 1 float4 each.
    const int loadRow  = tid >> 1;          // 0..127
    const int loadCol  = (tid & 1) * 4;     // 0 or 4
    const int aRowG    = bm + loadRow;
    const bool aValid  = (aRowG < MROWS);
    const int bRowG    = bn + loadRow;      // N=768 divisible by 128: always valid

    // Compute assignment: 16x16 thread grid, each 8x8
    const int tr = (tid >> 4) * 8;          // row offset in tile
    const int tc = (tid & 15) * 8;          // col offset in tile

    float acc[8][8];
    #pragma unroll
    for (int i = 0; i < 8; i++)
        #pragma unroll
        for (int j = 0; j < 8; j++)
            acc[i][j] = 0.0f;

    for (int k0 = 0; k0 < EDIM; k0 += 8) {
        float4 aReg = make_float4(0.f, 0.f, 0.f, 0.f);
        if (aValid)
            aReg = *reinterpret_cast<const float4*>(A + (size_t)aRowG * EDIM + k0 + loadCol);
        float4 bReg = *reinterpret_cast<const float4*>(B + (size_t)bRowG * EDIM + k0 + loadCol);

        __syncthreads();   // previous tile fully consumed before overwrite
        As[loadCol + 0][loadRow] = aReg.x;
        As[loadCol + 1][loadRow] = aReg.y;
        As[loadCol + 2][loadRow] = aReg.z;
        As[loadCol + 3][loadRow] = aReg.w;
        Bs[loadCol + 0][loadRow] = bReg.x;
        Bs[loadCol + 1][loadRow] = bReg.y;
        Bs[loadCol + 2][loadRow] = bReg.z;
        Bs[loadCol + 3][loadRow] = bReg.w;
        __syncthreads();

        #pragma unroll
        for (int kk = 0; kk < 8; kk++) {
            float ra[8], rb[8];
            #pragma unroll
            for (int i = 0; i < 8; i++) ra[i] = As[kk][tr + i];
            #pragma unroll
            for (int j = 0; j < 8; j++) rb[j] = Bs[kk][tc + j];
            #pragma unroll
            for (int i = 0; i < 8; i++)
                #pragma unroll
                for (int j = 0; j < 8; j++)
                    acc[i][j] = fmaf(ra[i], rb[j], acc[i][j]);
        }
    }

    // bias for this thread's 8 columns
    float bv[8];
    #pragma unroll
    for (int j = 0; j < 8; j++) bv[j] = bias[bn + tc + j];

    #pragma unroll
    for (int i = 0; i < 8; i++) {
        int row = bm + tr + i;
        if (row < MROWS) {
            float* crow = C + (size_t)row * EDIM + bn + tc;
            float4 v0 = make_float4(acc[i][0] + bv[0], acc[i][1] + bv[1],
                                    acc[i][2] + bv[2], acc[i][3] + bv[3]);
            float4 v1 = make_float4(acc[i][4] + bv[4], acc[i][5] + bv[5],
                                    acc[i][6] + bv[6], acc[i][7] + bv[7]);
            *reinterpret_cast<float4*>(crow + 0) = v0;
            *reinterpret_cast<float4*>(crow + 4) = v1;
        }
    }
}

// Fused QKV projection: blockIdx.z selects which of Q/K/V to compute.
__global__ __launch_bounds__(256, 2) void qkv_gemm_kernel(
    const float* __restrict__ x,
    const float* __restrict__ Wq, const float* __restrict__ bq,
    const float* __restrict__ Wk, const float* __restrict__ bk,
    const float* __restrict__ Wv, const float* __restrict__ bv)
{
    const float* W;
    const float* bias;
    float* C;
    if (blockIdx.z == 0)      { W = Wq; bias = bq; C = g_Q; }
    else if (blockIdx.z == 1) { W = Wk; bias = bk; C = g_K; }
    else                      { W = Wv; bias = bv; C = g_V; }
    gemm_nt_body(x, W, bias, C);
}

// Output projection: out = g_AO @ Wp^T + bp
__global__ __launch_bounds__(256, 2) void proj_gemm_kernel(
    const float* __restrict__ Wp, const float* __restrict__ bp,
    float* __restrict__ out)
{
    gemm_nt_body(g_AO, Wp, bp, out);
}

// ---------------------------------------------------------------------------
// Attention: one CTA per (b, h). K and V tiles (197x64 fp32) resident in
// smem (row-padded to 65 floats -> conflict-free strided access). Each warp
// owns Q rows r = warp, warp+8, ... For each row: energy (197 dots of 64),
// warp softmax, then P@V with the quirk scale 1/sqrt(E) folded in post-softmax.
// ---------------------------------------------------------------------------
#define KV_STRIDE 65
#define EROW_STRIDE 208
#define ATTN_SMEM_FLOATS (SEQ * KV_STRIDE * 2 + 8 * HD + 8 * EROW_STRIDE)
#define ATTN_SMEM_BYTES  (ATTN_SMEM_FLOATS * 4)

__global__ __launch_bounds__(256, 2) void attn_kernel()
{
    extern __shared__ float sm[];
    float* Ks = sm;                          // [197][65]
    float* Vs = Ks + SEQ * KV_STRIDE;        // [197][65]
    float* qs = Vs + SEQ * KV_STRIDE;        // [8][64]
    float* es = qs + 8 * HD;                 // [8][208]

    const int bh = blockIdx.x;
    const int b = bh / NH;
    const int h = bh % NH;
    const size_t base = (size_t)b * PERB + (size_t)h * PERH;
    const float* Qg = g_Q + base;
    const float* Kg = g_K + base;
    const float* Vg = g_V + base;
    float* Og = g_AO + base;

    const int tid = threadIdx.x;

    // Load K, V (contiguous 12608-float chunks) into padded smem
    for (int i = tid; i < PERH; i += 256) {
        int r = i >> 6;         // /64
        int c = i & 63;
        Ks[r * KV_STRIDE + c] = Kg[i];
        Vs[r * KV_STRIDE + c] = Vg[i];
    }
    __syncthreads();

    const int w = tid >> 5;
    const int lane = tid & 31;
    float* qrow = qs + w * HD;
    float* erow = es + w * EROW_STRIDE;

    for (int r = w; r < SEQ; r += 8) {
        // load this Q row into smem (broadcast source for all lanes)
        qrow[lane]      = Qg[r * HD + lane];
        qrow[lane + 32] = Qg[r * HD + lane + 32];
        __syncwarp();

        // energy row: lane handles columns j = lane, lane+32, ...
        float mx = -1e30f;
        for (int j = lane; j < SEQ; j += 32) {
            const float* kr = Ks + j * KV_STRIDE;
            float e = 0.0f;
            #pragma unroll 16
            for (int d = 0; d < HD; d++)
                e = fmaf(qrow[d], kr[d], e);
            erow[j] = e;
            mx = fmaxf(mx, e);
        }
        #pragma unroll
        for (int o = 16; o > 0; o >>= 1)
            mx = fmaxf(mx, __shfl_xor_sync(0xffffffffu, mx, o));

        float sum = 0.0f;
        for (int j = lane; j < SEQ; j += 32) {
            float p = __expf(erow[j] - mx);
            erow[j] = p;
            sum += p;
        }
        #pragma unroll
        for (int o = 16; o > 0; o >>= 1)
            sum += __shfl_xor_sync(0xffffffffu, sum, o);

        __syncwarp();   // erow[] fully written before all lanes read all j

        // Quirk: softmax first, THEN divide by sqrt(E). Fold into row scale.
        const float inv = 1.0f / (sum * 27.712812921102035f);   // sqrt(768)

        float a0 = 0.0f, a1 = 0.0f;
        for (int j = 0; j < SEQ; j++) {
            float p = erow[j];                       // broadcast
            a0 = fmaf(p, Vs[j * KV_STRIDE + lane],      a0);
            a1 = fmaf(p, Vs[j * KV_STRIDE + lane + 32], a1);
        }
        Og[r * HD + lane]      = a0 * inv;
        Og[r * HD + lane + 32] = a1 * inv;
        __syncwarp();   // converge before next iteration rewrites qrow/erow
    }
}

// ---------------------------------------------------------------------------
// Launch
// ---------------------------------------------------------------------------
extern "C" void kernel_launch(void* const* d_in, const int* in_sizes, int n_in,
                              void* d_out, int out_size)
{
    const float* x  = (const float*)d_in[0];
    const float* Wq = (const float*)d_in[1];
    const float* bq = (const float*)d_in[2];
    const float* Wk = (const float*)d_in[3];
    const float* bk = (const float*)d_in[4];
    const float* Wv = (const float*)d_in[5];
    const float* bv = (const float*)d_in[6];
    const float* Wp = (const float*)d_in[7];
    const float* bp = (const float*)d_in[8];
    float* out = (float*)d_out;

    // QKV: grid (N/128=6, ceil(M/128)=99, 3 weights)
    dim3 gridQKV(6, 99, 3);
    qkv_gemm_kernel<<<gridQKV, 256>>>(x, Wq, bq, Wk, bk, Wv, bv);

    // Attention: one CTA per (b,h)
    cudaFuncSetAttribute(attn_kernel,
                         cudaFuncAttributeMaxDynamicSharedMemorySize,
                         ATTN_SMEM_BYTES);
    attn_kernel<<<BATCH * NH, 256, ATTN_SMEM_BYTES>>>();

    // Projection
    dim3 gridP(6, 99, 1);
    proj_gemm_kernel<<<gridP, 256>>>(Wp, bp, out);
}